// round 9
// baseline (speedup 1.0000x reference)
#include <cuda_runtime.h>
#include <math_constants.h>
#include <stdint.h>

#define KCODES 512
#define DDIM   64
#define NROW   65536
#define QELEMS 4194304
#define NBLK   148
#define NTHR   256            // 8 warps
#define MAXROWS 448
#define SXS    132            // padded float stride per row-pair (16B aligned)
#define NSLOT  16             // 2 passes x 8 warps

__device__ double   g_partial[NBLK];
__device__ unsigned g_count = 0;

// smem floats: sx 29568 | sa 448 | mbb 16*448 | mbi 16*448 | sred 256 dbl
#define OFF_SA   29568
#define OFF_MBB  30016
#define OFF_MBI  37184
#define OFF_SRED 44352
#define SMEM_BYTES (OFF_SRED * 4 + 256 * 8)   // 179456 B

// ---- f32x2 packed helpers (lanes round exactly like scalar __fmaf_rn) ------
__device__ __forceinline__ unsigned long long pack2(float lo, float hi) {
    unsigned long long r;
    asm("mov.b64 %0, {%1, %2};" : "=l"(r) : "f"(lo), "f"(hi));
    return r;
}
__device__ __forceinline__ void unpack2(unsigned long long v, float& lo, float& hi) {
    asm("mov.b64 {%0, %1}, %2;" : "=f"(lo), "=f"(hi) : "l"(v));
}
__device__ __forceinline__ void fma2(unsigned long long& acc,
                                     unsigned long long a, unsigned long long b) {
    asm("fma.rn.f32x2 %0, %1, %2, %0;" : "+l"(acc) : "l"(a), "l"(b));
}

// ---------------------------------------------------------------------------
// Zero this block's encoding rows; enc base is only 4B-aligned.
// ---------------------------------------------------------------------------
__device__ __forceinline__ void zero_rows(float* __restrict__ enc,
                                          int row0, int nrows, int tid) {
    float* p = enc + (size_t)row0 * KCODES;
    int n = nrows * KCODES;
    uintptr_t a = (uintptr_t)p;
    int head = (int)((((a + 15) & ~(uintptr_t)15) - a) >> 2);
    if (tid < head) p[tid] = 0.0f;
    int n4 = (n - head) >> 2;
    int tail = (n - head) & 3;
    float4* v = (float4*)(p + head);
    float4 z = make_float4(0.f, 0.f, 0.f, 0.f);
    for (int i = tid; i < n4; i += NTHR) v[i] = z;
    if (tid >= 4 && tid - 4 < tail) p[head + 4 * n4 + (tid - 4)] = 0.0f;
}

// ---------------------------------------------------------------------------
// Codes-in-registers FFMA2 kernel.
//  - x tile staged in smem pair-interleaved: sx[p*SXS + 2d + s] = x[2p+s][d]
//  - lane owns code k = pass*256 + wid*32 + lane: w packed {w,w} in 64 u64 regs
//  - acc lanes = the two rows of a pair; LDS.128 broadcast feeds 2 rows x 2 d
// ---------------------------------------------------------------------------
__global__ void __launch_bounds__(NTHR, 1) vq_fused(
    const float* __restrict__ x,
    const float* __restrict__ w,
    float* __restrict__ out,       // out[0] = loss
    float* __restrict__ qout,
    float* __restrict__ enc)
{
    extern __shared__ float sm[];
    float*  sx   = sm;
    float*  sa   = sm + OFF_SA;
    float*  mbb  = sm + OFF_MBB;               // [16][448]
    int*    mbi  = (int*)(sm + OFF_MBI);       // [16][448]
    double* sred = (double*)(sm + OFF_SRED);   // [256]

    const int tid  = threadIdx.x;
    const int bid  = blockIdx.x;
    const int wid  = tid >> 5;
    const int lane = tid & 31;

    // Block -> contiguous 32-row rowsets: 136 x 14, 12 x 12
    const int cnt    = (bid < 136) ? 14 : 12;
    const int rs0    = (bid < 136) ? bid * 14 : 1904 + (bid - 136) * 12;
    const int row0   = rs0 * 32;
    const int nrows  = cnt * 32;
    const int npairs = nrows >> 1;

    // Zero-fill this block's enc rows (drains under compute)
    zero_rows(enc, row0, nrows, tid);

    // Stage x tile pair-interleaved. x layout [B=64,D=64,H=32,W=32]:
    // row n -> b*65536 + (n&1023) + d*1024; consecutive rows coalesce.
    for (int d = 0; d < DDIM; d++) {
        for (int rb = 0; rb < nrows; rb += NTHR) {
            int r = rb + tid;
            if (r < nrows) {
                int n = row0 + r, b = n >> 10, hw = n & 1023;
                sx[(r >> 1) * SXS + 2 * d + (r & 1)] =
                    x[(size_t)b * 65536 + hw + (size_t)d * 1024];
            }
        }
    }
    __syncthreads();

    // Row norms a = sum fl(x^2), sequential (reference rounding chain)
    for (int r = tid; r < nrows; r += NTHR) {
        const float* pr = sx + (r >> 1) * SXS + (r & 1);
        float acc = 0.0f;
        #pragma unroll
        for (int d = 0; d < DDIM; d++)
            acc = __fadd_rn(acc, __fmul_rn(pr[2 * d], pr[2 * d]));
        sa[r] = acc;
    }
    __syncthreads();

    // ---------------- Main: 2 passes x (1 code per lane) -------------------
    #pragma unroll 1
    for (int s = 0; s < 2; s++) {
        const int k = s * 256 + wid * 32 + lane;

        // Load this lane's code: pack {w,w}; norm via sequential chain
        unsigned long long wq[DDIM];
        float bk = 0.0f;
        {
            const float4* wr = (const float4*)(w + (size_t)k * DDIM);
            #pragma unroll
            for (int j = 0; j < 16; j++) {
                float4 v = wr[j];
                wq[4*j + 0] = pack2(v.x, v.x);
                wq[4*j + 1] = pack2(v.y, v.y);
                wq[4*j + 2] = pack2(v.z, v.z);
                wq[4*j + 3] = pack2(v.w, v.w);
                bk = __fadd_rn(bk, __fmul_rn(v.x, v.x));
                bk = __fadd_rn(bk, __fmul_rn(v.y, v.y));
                bk = __fadd_rn(bk, __fmul_rn(v.z, v.z));
                bk = __fadd_rn(bk, __fmul_rn(v.w, v.w));
            }
        }

        #pragma unroll 1
        for (int p = 0; p < npairs; p++) {
            const ulonglong2* xp = (const ulonglong2*)(sx + p * SXS);
            unsigned long long acc = 0ull;
            #pragma unroll
            for (int j = 0; j < 32; j++) {
                ulonglong2 X = xp[j];          // {x0[2j],x1[2j]},{x0[2j+1],x1[2j+1]}
                fma2(acc, X.x, wq[2*j]);
                fma2(acc, X.y, wq[2*j + 1]);
            }
            float m0, m1;
            unpack2(acc, m0, m1);
            float2 av = *(const float2*)(sa + 2 * p);
            // d = fl( fl(a + b) - fl(2*m) ) — exact reference rounding
            float d0 = __fsub_rn(__fadd_rn(av.x, bk), __fmul_rn(2.0f, m0));
            float d1 = __fsub_rn(__fadd_rn(av.y, bk), __fmul_rn(2.0f, m1));
            int k0 = k, k1 = k;
            // Exact min-k argmin across the warp's 32 codes
            #pragma unroll
            for (int m = 1; m < 32; m <<= 1) {
                float od0 = __shfl_xor_sync(0xffffffffu, d0, m);
                int   ok0 = __shfl_xor_sync(0xffffffffu, k0, m);
                if (od0 < d0 || (od0 == d0 && ok0 < k0)) { d0 = od0; k0 = ok0; }
                float od1 = __shfl_xor_sync(0xffffffffu, d1, m);
                int   ok1 = __shfl_xor_sync(0xffffffffu, k1, m);
                if (od1 < d1 || (od1 == d1 && ok1 < k1)) { d1 = od1; k1 = ok1; }
            }
            if (lane == 0) {
                int slot = s * 8 + wid;        // ascending slot == ascending k
                mbb[slot * MAXROWS + 2*p]     = d0;
                mbi[slot * MAXROWS + 2*p]     = k0;
                mbb[slot * MAXROWS + 2*p + 1] = d1;
                mbi[slot * MAXROWS + 2*p + 1] = k1;
            }
        }
    }
    __syncthreads();

    // ---------------- Epilogue: merge slots + outputs ----------------------
    double ls = 0.0;
    for (int rl = tid; rl < nrows; rl += NTHR) {
        float best = CUDART_INF_F; int bi = 0;
        #pragma unroll
        for (int sl = 0; sl < NSLOT; sl++) {
            float d = mbb[sl * MAXROWS + rl];
            int   kk = mbi[sl * MAXROWS + rl];
            if (d < best) { best = d; bi = kk; }   // ascending k: first index
        }
        const int n = row0 + rl;
        const int b = n >> 10, hw = n & 1023;
        const float* xr = sx + (rl >> 1) * SXS + (rl & 1);
        float*       qp = qout + (size_t)b * 65536 + hw;
        const float* wq = w + (size_t)bi * DDIM;   // L2-hot
        #pragma unroll
        for (int d = 0; d < DDIM; d++) {
            float xv   = xr[2 * d];
            float diff = __fsub_rn(wq[d], xv);
            qp[(size_t)d * 1024] = __fadd_rn(xv, diff);   // straight-through
            ls += (double)__fmul_rn(diff, diff);
        }
        enc[(size_t)n * KCODES + bi] = 1.0f;
    }

    // Deterministic block-level loss reduction (fixed tree)
    sred[tid] = ls;
    __syncthreads();
    for (int s = NTHR / 2; s > 0; s >>= 1) {
        if (tid < s) sred[tid] += sred[tid + s];
        __syncthreads();
    }

    // Last-block final reduce (fence+atomic; deterministic fixed-order sum)
    __shared__ int isLast;
    if (tid == 0) {
        g_partial[bid] = sred[0];
        __threadfence();
        unsigned old = atomicAdd(&g_count, 1u);
        isLast = (old == NBLK - 1u) ? 1 : 0;
    }
    __syncthreads();
    if (isLast) {
        sred[tid] = (tid < NBLK) ? g_partial[tid] : 0.0;
        __syncthreads();
        for (int s = NTHR / 2; s > 0; s >>= 1) {
            if (tid < s) sred[tid] += sred[tid + s];
            __syncthreads();
        }
        if (tid == 0) {
            float m = (float)(sred[0] / (double)QELEMS);
            out[0] = __fadd_rn(m, __fmul_rn(0.25f, m));  // z_q + 0.25*z_e
            g_count = 0;                                 // reset for replay
        }
    }
}

// ---------------------------------------------------------------------------
extern "C" void kernel_launch(void* const* d_in, const int* in_sizes, int n_in,
                              void* d_out, int out_size) {
    const float* x = (const float*)d_in[0];   // [64,64,32,32] fp32
    const float* w = (const float*)d_in[1];   // [512,64] fp32
    float* out  = (float*)d_out;
    float* qout = out + 1;                    // [4194304] (4B-aligned only)
    float* enc  = out + 1 + QELEMS;           // [65536*512] (4B-aligned only)

    cudaFuncSetAttribute(vq_fused, cudaFuncAttributeMaxDynamicSharedMemorySize,
                         SMEM_BYTES);

    vq_fused<<<NBLK, NTHR, SMEM_BYTES>>>(x, w, out, qout, enc);
}